// round 1
// baseline (speedup 1.0000x reference)
#include <cuda_runtime.h>
#include <cstdint>
#include <cstddef>

// Correlation cost volume:
//   out[b,i,h,x] = (1/128) * sum_c L[b,c,h,x] * R[b,c,h,x-i],  x>=i, else 0
// b=8, c=128, h=96, w=320, D=48.
//
// Block: 8 (b,h) rows x one 64-wide x-tile. Thread tile: 8 x * 8 disparities.
// Double-buffered cp.async over c-chunks of 16. Swizzled smem (conflict-free
// LDS.128). Right halo zero-filled via cp.async src-size=0 -> x<i outputs are
// exactly zero with no special casing.

namespace {
constexpr int kB = 8, kC = 128, kH = 96, kW = 320, kD = 48;
constexpr int R_PER_BLK = 8;            // (b,h) rows per block
constexpr int TX = 64;                  // x-tile width
constexpr int CCH = 16;                 // channels per chunk
constexpr int NCHUNK = kC / CCH;        // 8
constexpr int TRW = TX + kD;            // 112 right tile width
constexpr int LROWB = TX * 4;           // 256 B per (row,c) left line
constexpr int RROWB = TRW * 4;          // 448 B per (row,c) right line
constexpr int LBYTES = R_PER_BLK * CCH * LROWB;   // 32768
constexpr int RBYTES = R_PER_BLK * CCH * RROWB;   // 57344
constexpr int BUFB   = LBYTES + RBYTES;           // 90112
constexpr int NT = 384;                 // 12 warps -> 3 per SMSP
constexpr int LGRAN = R_PER_BLK * CCH * (TX / 4);   // 2048
constexpr int RGRAN = R_PER_BLK * CCH * (TRW / 4);  // 3584
constexpr int TGRAN = LGRAN + RGRAN;                // 5632
}

// Granule (16B) swizzle: for any 8-lane phase reading 8 consecutive
// same-parity granules, P(g)%8 is a permutation -> conflict-free LDS.128.
__device__ __forceinline__ uint32_t swz16(uint32_t g) { return g ^ ((g >> 3) & 1u); }

__device__ __forceinline__ void cp_async16(uint32_t dst, const float* src, uint32_t nbytes) {
    asm volatile("cp.async.cg.shared.global [%0], [%1], 16, %2;\n"
                 :: "r"(dst), "l"(src), "r"(nbytes));
}
__device__ __forceinline__ void cp_commit() { asm volatile("cp.async.commit_group;\n" ::: "memory"); }
template <int N>
__device__ __forceinline__ void cp_wait() { asm volatile("cp.async.wait_group %0;\n" :: "n"(N) : "memory"); }

extern __shared__ float smem_f[];

__global__ __launch_bounds__(NT, 1)
void costvol_kernel(const float* __restrict__ L, const float* __restrict__ R,
                    float* __restrict__ out) {
    const int tid = threadIdx.x;
    const int X  = blockIdx.x * TX;          // x-tile start
    const int rg = blockIdx.y;               // row group (8 rows)

    const uint32_t smemU = (uint32_t)__cvta_generic_to_shared(smem_f);
    char* smem = (char*)smem_f;

    // Compute-thread coordinates: xg fastest (coalesced/conflict-free lanes)
    const int xg = tid & 7;                  // x group (8 x each)
    const int r  = (tid >> 3) & 7;           // row within block
    const int ig = tid >> 6;                 // disparity group 0..5 (8 i each)

    const int rho = rg * R_PER_BLK + r;
    const int b = rho / kH;
    const int h = rho - b * kH;

    float acc[8][8];
#pragma unroll
    for (int a = 0; a < 8; a++)
#pragma unroll
        for (int c2 = 0; c2 < 8; c2++) acc[a][c2] = 0.0f;

    // -------- producer: stage one c-chunk into smem buffer --------
    auto produce = [&](int chunk, int buf) {
        const int c0 = chunk * CCH;
        const uint32_t base = smemU + (uint32_t)buf * BUFB;
        for (int idx = tid; idx < TGRAN; idx += NT) {
            if (idx < LGRAN) {
                const int g   = idx & 15;        // granule within left line
                const int row = idx >> 4;        // r2*16 + cc
                const int cc  = row & 15;
                const int r2  = row >> 4;
                const int rho2 = rg * R_PER_BLK + r2;
                const int b2 = rho2 / kH;
                const int h2 = rho2 - b2 * kH;
                const float* src = L + ((size_t)((b2 * kC + c0 + cc) * kH + h2)) * kW
                                     + X + g * 4;
                const uint32_t dst = base + (uint32_t)row * LROWB + swz16(g) * 16;
                cp_async16(dst, src, 16u);
            } else {
                const int j   = idx - LGRAN;
                const int g   = j % 28;          // granule within right line
                const int row = j / 28;
                const int cc  = row & 15;
                const int r2  = row >> 4;
                const int rho2 = rg * R_PER_BLK + r2;
                const int b2 = rho2 / kH;
                const int h2 = rho2 - b2 * kH;
                const int xs = X - kD + g * 4;   // may be negative only when X==0
                const float* rowp = R + ((size_t)((b2 * kC + c0 + cc) * kH + h2)) * kW;
                const uint32_t dst = base + LBYTES + (uint32_t)row * RROWB + swz16(g) * 16;
                cp_async16(dst, rowp + (xs > 0 ? xs : 0), xs >= 0 ? 16u : 0u);  // 0 => zero-fill
            }
        }
        cp_commit();
    };

    // -------- consumer setup: per-thread swizzled smem offsets --------
    const uint32_t offL0 = swz16(2u * xg)      * 16u;
    const uint32_t offL1 = swz16(2u * xg + 1u) * 16u;
    const int gR0 = 10 + 2 * (xg - ig);        // window start granule (>=0)
    const uint32_t offR0 = swz16(gR0)     * 16u;
    const uint32_t offR1 = swz16(gR0 + 1) * 16u;
    const uint32_t offR2 = swz16(gR0 + 2) * 16u;
    const uint32_t offR3 = swz16(gR0 + 3) * 16u;

    auto compute = [&](int buf) {
        const char* sL = smem + (size_t)buf * BUFB + (size_t)r * (CCH * LROWB);
        const char* sR = smem + (size_t)buf * BUFB + LBYTES + (size_t)r * (CCH * RROWB);
#pragma unroll 2
        for (int cc = 0; cc < CCH; cc++) {
            const float4 l0 = *(const float4*)(sL + cc * LROWB + offL0);
            const float4 l1 = *(const float4*)(sL + cc * LROWB + offL1);
            const float4 q0 = *(const float4*)(sR + cc * RROWB + offR0);
            const float4 q1 = *(const float4*)(sR + cc * RROWB + offR1);
            const float4 q2 = *(const float4*)(sR + cc * RROWB + offR2);
            const float4 q3 = *(const float4*)(sR + cc * RROWB + offR3);
            const float Lf[8] = {l0.x, l0.y, l0.z, l0.w, l1.x, l1.y, l1.z, l1.w};
            const float Rw[16] = {q0.x, q0.y, q0.z, q0.w, q1.x, q1.y, q1.z, q1.w,
                                  q2.x, q2.y, q2.z, q2.w, q3.x, q3.y, q3.z, q3.w};
            // k = 48 + 8*(xg-ig) + dx - di ; window float index = k - wstart = 8+dx-di
#pragma unroll
            for (int di = 0; di < 8; di++)
#pragma unroll
                for (int dx = 0; dx < 8; dx++)
                    acc[di][dx] = fmaf(Lf[dx], Rw[8 + dx - di], acc[di][dx]);
        }
    };

    // -------- double-buffered pipeline over c-chunks --------
    produce(0, 0);
    int buf = 0;
#pragma unroll 1
    for (int k = 0; k < NCHUNK; k++) {
        if (k + 1 < NCHUNK) {
            produce(k + 1, buf ^ 1);
            cp_wait<1>();
        } else {
            cp_wait<0>();
        }
        __syncthreads();
        compute(buf);
        __syncthreads();   // protect buf before it is re-filled next iteration
        buf ^= 1;
    }

    // -------- epilogue: mean over C, vectorized stores --------
    const float scale = 1.0f / (float)kC;
    float* obase = out + ((size_t)(b * kD + ig * 8) * kH + h) * kW + X + xg * 8;
#pragma unroll
    for (int di = 0; di < 8; di++) {
        float4 v0, v1;
        v0.x = acc[di][0] * scale; v0.y = acc[di][1] * scale;
        v0.z = acc[di][2] * scale; v0.w = acc[di][3] * scale;
        v1.x = acc[di][4] * scale; v1.y = acc[di][5] * scale;
        v1.z = acc[di][6] * scale; v1.w = acc[di][7] * scale;
        float* op = obase + (size_t)di * (kH * kW);
        *(float4*)(op)     = v0;
        *(float4*)(op + 4) = v1;
    }
}

extern "C" void kernel_launch(void* const* d_in, const int* in_sizes, int n_in,
                              void* d_out, int out_size) {
    const float* L = (const float*)d_in[0];
    const float* R = (const float*)d_in[1];
    float* out = (float*)d_out;

    cudaFuncSetAttribute(costvol_kernel,
                         cudaFuncAttributeMaxDynamicSharedMemorySize, 2 * BUFB);

    dim3 grid(kW / TX, (kB * kH) / R_PER_BLK);   // (5, 96) = 480 blocks
    costvol_kernel<<<grid, NT, 2 * BUFB>>>(L, R, out);
}

// round 2
// speedup vs baseline: 1.1309x; 1.1309x over previous
#include <cuda_runtime.h>
#include <cstdint>
#include <cstddef>

// Correlation cost volume:
//   out[b,i,h,x] = (1/128) * sum_c L[b,c,h,x] * R[b,c,h,x-i],  x>=i, else 0
// b=8, c=128, h=96, w=320, D=48.
//
// R2: f32x2 packed FFMA (PTX-only FFMA2), 960 small CTAs (2/SM) for wave
// balance, shift/mask-only producer addressing (R rows padded to 512B).

namespace {
constexpr int kB = 8, kC = 128, kH = 96, kW = 320, kD = 48;
constexpr int CHW = kH * kW;            // 30720
constexpr int R_PER_BLK = 4;            // (b,h) rows per block
constexpr int TX = 64;                  // x-tile width
constexpr int CCH = 16;                 // channels per chunk
constexpr int NCHUNK = kC / CCH;        // 8
constexpr int LROWB = TX * 4;           // 256 B per (row,c) left line (16 granules)
constexpr int RROWB = 512;              // right line padded to 32 granules (28 used)
constexpr int ROWS_PER_CHUNK = R_PER_BLK * CCH;        // 64
constexpr int LBYTES = ROWS_PER_CHUNK * LROWB;         // 16384
constexpr int RBYTES = ROWS_PER_CHUNK * RROWB;         // 32768
constexpr int BUFB   = LBYTES + RBYTES;                // 49152
constexpr int NT = 192;                 // 6 warps: warp = 8 xg x 4 r, one ig each
constexpr int LSLOTS = ROWS_PER_CHUNK * 16;            // 1024
constexpr int RSLOTS = ROWS_PER_CHUNK * 32;            // 2048 (28/32 issued)
}

// Granule (16B) swizzle: 8 consecutive same-parity granules -> permutation mod 8.
__device__ __forceinline__ uint32_t swz16(uint32_t g) { return g ^ ((g >> 3) & 1u); }

__device__ __forceinline__ void cp_async16(uint32_t dst, const float* src, uint32_t nbytes) {
    asm volatile("cp.async.cg.shared.global [%0], [%1], 16, %2;\n"
                 :: "r"(dst), "l"(src), "r"(nbytes));
}
__device__ __forceinline__ void cp_commit() { asm volatile("cp.async.commit_group;\n" ::: "memory"); }
template <int N>
__device__ __forceinline__ void cp_wait() { asm volatile("cp.async.wait_group %0;\n" :: "n"(N) : "memory"); }

// Packed f32x2 FMA: d = a*b + d (elementwise on fp32 pairs). PTX-only on sm_103a.
__device__ __forceinline__ void ffma2(unsigned long long& d,
                                      unsigned long long a, unsigned long long b) {
    asm("fma.rn.f32x2 %0, %1, %2, %0;" : "+l"(d) : "l"(a), "l"(b));
}
// Odd pair: (hi32(a), lo32(b)).
__device__ __forceinline__ unsigned long long mkO(unsigned long long a,
                                                  unsigned long long b) {
    unsigned long long o;
    asm("{\n\t.reg .b32 al, ah, bl, bh;\n\t"
        "mov.b64 {al, ah}, %1;\n\t"
        "mov.b64 {bl, bh}, %2;\n\t"
        "mov.b64 %0, {ah, bl};\n\t}"
        : "=l"(o) : "l"(a), "l"(b));
    return o;
}
__device__ __forceinline__ void unpack2(float& lo, float& hi, unsigned long long v) {
    asm("mov.b64 {%0, %1}, %2;" : "=f"(lo), "=f"(hi) : "l"(v));
}

extern __shared__ float smem_f[];

__global__ __launch_bounds__(NT, 2)
void costvol_kernel(const float* __restrict__ L, const float* __restrict__ R,
                    float* __restrict__ out) {
    const int tid = threadIdx.x;
    const int X  = blockIdx.x * TX;          // x-tile start
    const int rg = blockIdx.y;               // row group (4 (b,h) rows)

    const uint32_t smemU = (uint32_t)__cvta_generic_to_shared(smem_f);
    char* smem = (char*)smem_f;

    // Compute-thread coordinates (warp = 8 xg x 4 r, fixed ig)
    const int xg = tid & 7;                  // x group (8 x each)
    const int r  = (tid >> 3) & 3;           // row within block
    const int ig = tid >> 5;                 // disparity group 0..5 (8 i each)

    // 96 % 4 == 0 -> all 4 rows of a block share the same batch b.
    const int b  = rg / (kH / R_PER_BLK);    // rg / 24
    const int h0 = (rg % (kH / R_PER_BLK)) * R_PER_BLK;
    const int h  = h0 + r;

    // Global base pointers for this block's row group (c0 added per chunk).
    const float* Lblk = L + ((size_t)(b * kC) * kH + h0) * kW + X;
    const float* Rblk = R + ((size_t)(b * kC) * kH + h0) * kW;   // x=0 of rows

    unsigned long long acc2[8][4];
#pragma unroll
    for (int a = 0; a < 8; a++)
#pragma unroll
        for (int j = 0; j < 4; j++) acc2[a][j] = 0ull;

    // -------- producer: stage one c-chunk (16 channels) --------
    auto produce = [&](int chunk, int buf) {
        const int c0f = chunk * CCH * CHW;           // float offset of chunk
        const uint32_t base = smemU + (uint32_t)buf * BUFB;
        // Left: 1024 granules; row = r2*16+cc, g = idx&15
#pragma unroll 1
        for (int idx = tid; idx < LSLOTS; idx += NT) {
            const int g   = idx & 15;
            const int row = idx >> 4;
            const int cc  = row & 15;
            const int r2  = row >> 4;
            const float* src = Lblk + c0f + cc * CHW + r2 * kW + g * 4;
            cp_async16(base + (uint32_t)row * LROWB + swz16(g) * 16, src, 16u);
        }
        // Right: rows padded to 32 granules, 28 real; window starts at x = X-48
#pragma unroll 1
        for (int idx = tid; idx < RSLOTS; idx += NT) {
            const int g   = idx & 31;
            const int row = idx >> 5;
            if (g < 28) {
                const int cc = row & 15;
                const int r2 = row >> 4;
                const int xs = X - kD + g * 4;       // absolute x (may be <0 only at X=0)
                const float* rowp = Rblk + c0f + cc * CHW + r2 * kW;
                cp_async16(base + LBYTES + (uint32_t)row * RROWB + swz16(g) * 16,
                           rowp + (xs > 0 ? xs : 0), xs >= 0 ? 16u : 0u);
            }
        }
        cp_commit();
    };

    // -------- consumer: per-thread swizzled smem offsets --------
    const uint32_t offL0 = swz16(2u * xg)      * 16u;
    const uint32_t offL1 = swz16(2u * xg + 1u) * 16u;
    const int gR0 = 10 + 2 * (xg - ig);        // window start granule in [0,24]
    const uint32_t offR0 = swz16(gR0)     * 16u;
    const uint32_t offR1 = swz16(gR0 + 1) * 16u;
    const uint32_t offR2 = swz16(gR0 + 2) * 16u;
    const uint32_t offR3 = swz16(gR0 + 3) * 16u;

    auto compute = [&](int buf) {
        const char* sL = smem + (size_t)buf * BUFB + (size_t)r * (16 * LROWB);
        const char* sR = smem + (size_t)buf * BUFB + LBYTES + (size_t)r * (16 * RROWB);
#pragma unroll 2
        for (int cc = 0; cc < CCH; cc++) {
            // L: 8 floats = 4 natural even pairs
            const ulonglong2 la = *(const ulonglong2*)(sL + cc * LROWB + offL0);
            const ulonglong2 lb = *(const ulonglong2*)(sL + cc * LROWB + offL1);
            const unsigned long long Lp[4] = {la.x, la.y, lb.x, lb.y};
            // R window: 16 floats = 8 natural even pairs E, 7 packed odd pairs O
            const ulonglong2 q0 = *(const ulonglong2*)(sR + cc * RROWB + offR0);
            const ulonglong2 q1 = *(const ulonglong2*)(sR + cc * RROWB + offR1);
            const ulonglong2 q2 = *(const ulonglong2*)(sR + cc * RROWB + offR2);
            const ulonglong2 q3 = *(const ulonglong2*)(sR + cc * RROWB + offR3);
            const unsigned long long E[8] = {q0.x, q0.y, q1.x, q1.y,
                                             q2.x, q2.y, q3.x, q3.y};
            unsigned long long O[7];
#pragma unroll
            for (int t = 0; t < 7; t++) O[t] = mkO(E[t], E[t + 1]);
            // Rw[w] = right float at window index w; pair for (di, dx=2j..2j+1)
            // needs (Rw[8+2j-di], Rw[9+2j-di]):
            //   di=2m   -> E[4+j-m];  di=2m+1 -> O[3+j-m]
#pragma unroll
            for (int m = 0; m < 4; m++)
#pragma unroll
                for (int j = 0; j < 4; j++) {
                    ffma2(acc2[2 * m][j],     Lp[j], E[4 + j - m]);
                    ffma2(acc2[2 * m + 1][j], Lp[j], O[3 + j - m]);
                }
        }
    };

    // -------- double-buffered pipeline over c-chunks --------
    produce(0, 0);
    int buf = 0;
#pragma unroll 1
    for (int k = 0; k < NCHUNK; k++) {
        if (k + 1 < NCHUNK) {
            produce(k + 1, buf ^ 1);
            cp_wait<1>();
        } else {
            cp_wait<0>();
        }
        __syncthreads();
        compute(buf);
        __syncthreads();   // protect buf before refill next iteration
        buf ^= 1;
    }

    // -------- epilogue: mean over C, vectorized stores --------
    const float scale = 1.0f / (float)kC;
    float* obase = out + ((size_t)(b * kD + ig * 8) * kH + h) * kW + X + xg * 8;
#pragma unroll
    for (int di = 0; di < 8; di++) {
        float4 v0, v1;
        float p0, p1;
        unpack2(p0, p1, acc2[di][0]); v0.x = p0 * scale; v0.y = p1 * scale;
        unpack2(p0, p1, acc2[di][1]); v0.z = p0 * scale; v0.w = p1 * scale;
        unpack2(p0, p1, acc2[di][2]); v1.x = p0 * scale; v1.y = p1 * scale;
        unpack2(p0, p1, acc2[di][3]); v1.z = p0 * scale; v1.w = p1 * scale;
        float* op = obase + (size_t)di * CHW;
        *(float4*)(op)     = v0;
        *(float4*)(op + 4) = v1;
    }
}

extern "C" void kernel_launch(void* const* d_in, const int* in_sizes, int n_in,
                              void* d_out, int out_size) {
    const float* L = (const float*)d_in[0];
    const float* R = (const float*)d_in[1];
    float* out = (float*)d_out;

    cudaFuncSetAttribute(costvol_kernel,
                         cudaFuncAttributeMaxDynamicSharedMemorySize, 2 * BUFB);

    dim3 grid(kW / TX, (kB * kH) / R_PER_BLK);   // (5, 192) = 960 blocks
    costvol_kernel<<<grid, NT, 2 * BUFB>>>(L, R, out);
}